// round 3
// baseline (speedup 1.0000x reference)
#include <cuda_runtime.h>
#include <math.h>
#include <stdint.h>

#define BB   16
#define SS   2048
#define DD   768
#define MHID 128
#define NTOK (BB*SS)
#define TM   64
#define OFF_A (NTOK*DD)            // h_prime elements
#define OFF_B (OFF_A + NTOK*10)    // + d_a elements

#define M_TOT  247357937827LL
#define M_HALF 123678968913LL      // M//2 (M odd)

static __device__ int   g_op[BB];
static __device__ float g_eq[BB];

__device__ const int d_P[9] = {7,11,13,17,19,23,29,31,37};
__device__ const float d_P10F[9][10] = {
  {1,3,2,6,4,5,1,3,2,6},
  {1,10,1,10,1,10,1,10,1,10},
  {1,10,9,12,3,4,1,10,9,12},
  {1,10,15,14,4,6,9,5,16,7},
  {1,10,5,12,6,3,11,15,17,18},
  {1,10,8,11,18,19,6,14,2,20},
  {1,10,13,14,24,8,22,17,25,18},
  {1,10,7,8,18,25,2,20,14,16},
  {1,10,26,1,10,26,1,10,26,1}};
__device__ const long long d_CRT[9] = {
  35336848261LL, 224870852570LL, 114165202074LL, 218257003965LL,
  78113032998LL, 53773464745LL, 68236672504LL, 223420072876LL,
  220616539143LL};

// TF32 operand rounding (JAX on GPU defaults f32 matmul to TF32).
__device__ __forceinline__ float tf32r(float x) {
  uint32_t u;
  asm("cvt.rna.tf32.f32 %0, %1;" : "=r"(u) : "f"(x));
  return __uint_as_float(u);
}

__device__ __forceinline__ long long modpow6(long long base, long long e, long long p) {
  long long res = 1, b = base % p;
  #pragma unroll
  for (int i = 0; i < 6; i++) {
    if (e & 1) res = res * b % p;
    b = b * b % p;
    e >>= 1;
  }
  return res;
}

// ---------------------------------------------------------------------------
// Prep: per-batch op index (first token in [20,25)) and has_eq (any token==28)
// NOTE: harness delivers int64 JAX arrays as int32.
// ---------------------------------------------------------------------------
__global__ void prep_kernel(const int* __restrict__ ids) {
  int w = threadIdx.x >> 5, lane = threadIdx.x & 31;
  if (w >= BB) return;
  const int* row = ids + w * SS;
  int minpos = SS, eq = 0;
  for (int i = lane; i < SS; i += 32) {
    int t = row[i];
    eq |= (t == 28);
    if (t >= 20 && t <= 24) minpos = min(minpos, i);
  }
  #pragma unroll
  for (int off = 16; off; off >>= 1) {
    minpos = min(minpos, __shfl_xor_sync(0xffffffffu, minpos, off));
    eq    |= __shfl_xor_sync(0xffffffffu, eq, off);
  }
  if (lane == 0) {
    int pos = (minpos < SS) ? minpos : 0;
    int t = row[pos];
    g_op[w] = (t >= 20 && t <= 24) ? (t - 20) : -1;
    g_eq[w] = eq ? 1.0f : 0.0f;
  }
}

// ---------------------------------------------------------------------------
// Main fused kernel: 64 tokens / block, 256 threads
// ---------------------------------------------------------------------------
struct SmemT {
  float sAT[32][68];    // A chunk transposed [k][token] (+pad), TF32-rounded
  float sB[32][128];    // W1 chunk [k][col], TF32-rounded
  float sHid[64][128];  // relu(h@W1+b1), TF32-rounded for GEMM2
  float sW2[32*240];    // W2 chunk regrouped [j][cg*12+cc], TF32-rounded
  float sDig[64*20];    // soft digits (d_a: 0..9, d_b: 10..19)
  int   sRes[64*9];     // selected-op residue per prime
  float sMsb[64*12];    // msb-reordered digits + sign
};

__global__ void __launch_bounds__(256, 2)
main_kernel(const float* __restrict__ h,  const float* __restrict__ W1,
            const float* __restrict__ b1, const float* __restrict__ W2,
            const float* __restrict__ b2, const float* __restrict__ Winj,
            const float* __restrict__ binj, const float* __restrict__ gatep,
            float* __restrict__ out) {
  extern __shared__ char smem_raw[];
  SmemT* s = reinterpret_cast<SmemT*>(smem_raw);
  const int tid   = threadIdx.x;
  const int tok0  = blockIdx.x * TM;
  const int batch = tok0 / SS;

  // ============================ GEMM1: hid = relu(h@W1+b1) ==================
  const int tt = tid >> 5;  // token octet 0..7
  const int tc = tid & 31;  // col quad   0..31
  float acc[8][4];
  #pragma unroll
  for (int j = 0; j < 8; j++)
    #pragma unroll
    for (int i = 0; i < 4; i++) acc[j][i] = 0.0f;

  for (int k0 = 0; k0 < DD; k0 += 32) {
    #pragma unroll
    for (int r = 0; r < 2; r++) {        // A: 64x32 = 512 float4
      int f4 = tid + r * 256;
      int row = f4 >> 3, c4 = f4 & 7;
      float4 v = *(const float4*)(h + (long long)(tok0 + row) * DD + k0 + c4 * 4);
      s->sAT[c4*4+0][row] = tf32r(v.x); s->sAT[c4*4+1][row] = tf32r(v.y);
      s->sAT[c4*4+2][row] = tf32r(v.z); s->sAT[c4*4+3][row] = tf32r(v.w);
    }
    #pragma unroll
    for (int r = 0; r < 4; r++) {        // B: 32x128 = 1024 float4
      int f4 = tid + r * 256;
      int row = f4 >> 5, c4 = f4 & 31;
      float4 v = *(const float4*)(W1 + (k0 + row) * MHID + c4 * 4);
      v.x = tf32r(v.x); v.y = tf32r(v.y); v.z = tf32r(v.z); v.w = tf32r(v.w);
      *(float4*)(&s->sB[row][c4*4]) = v;
    }
    __syncthreads();
    #pragma unroll
    for (int kk = 0; kk < 32; kk++) {
      float4 a0 = *(const float4*)(&s->sAT[kk][tt*8]);
      float4 a1 = *(const float4*)(&s->sAT[kk][tt*8+4]);
      float4 bv = *(const float4*)(&s->sB[kk][tc*4]);
      float av[8] = {a0.x,a0.y,a0.z,a0.w,a1.x,a1.y,a1.z,a1.w};
      float bb[4] = {bv.x,bv.y,bv.z,bv.w};
      #pragma unroll
      for (int j = 0; j < 8; j++)
        #pragma unroll
        for (int i = 0; i < 4; i++)
          acc[j][i] = fmaf(av[j], bb[i], acc[j][i]);
    }
    __syncthreads();
  }
  {
    float bb[4];
    #pragma unroll
    for (int i = 0; i < 4; i++) bb[i] = b1[tc*4+i];
    #pragma unroll
    for (int j = 0; j < 8; j++) {
      float4 v;
      // relu(hid) then TF32-round: operand quantization GEMM2 sees.
      v.x = tf32r(fmaxf(acc[j][0] + bb[0], 0.0f));
      v.y = tf32r(fmaxf(acc[j][1] + bb[1], 0.0f));
      v.z = tf32r(fmaxf(acc[j][2] + bb[2], 0.0f));
      v.w = tf32r(fmaxf(acc[j][3] + bb[3], 0.0f));
      *(float4*)(&s->sHid[tt*8+j][tc*4]) = v;
    }
  }
  __syncthreads();

  // ====================== GEMM2 + softmax -> soft digits ====================
  float lg[5][10];
  #pragma unroll
  for (int t = 0; t < 5; t++)
    #pragma unroll
    for (int c = 0; c < 10; c++) lg[t][c] = 0.0f;

  for (int ch = 0; ch < 4; ch++) {       // K chunks of 32
    if (ch) __syncthreads();
    for (int i4 = tid; i4 < 1600; i4 += 256) {  // 32 rows * 50 float4
      int row = i4 / 50, c4 = i4 % 50;
      float4 v = *(const float4*)(W2 + (ch*32 + row) * 200 + c4 * 4);
      float vv[4] = {tf32r(v.x), tf32r(v.y), tf32r(v.z), tf32r(v.w)};
      #pragma unroll
      for (int u = 0; u < 4; u++) {
        int c = c4 * 4 + u;
        s->sW2[row*240 + (c/10)*12 + (c%10)] = vv[u];
      }
    }
    __syncthreads();
    #pragma unroll
    for (int t = 0; t < 5; t++) {
      int task = tid + t * 256;
      int tok = task / 20, cg = task % 20;
      const float* wb = &s->sW2[cg*12];
      const float* hb = &s->sHid[tok][ch*32];
      #pragma unroll 8
      for (int j = 0; j < 32; j++) {
        float hv = hb[j];
        float4 w0 = *(const float4*)(wb + j*240);
        float4 w1 = *(const float4*)(wb + j*240 + 4);
        float2 w2v = *(const float2*)(wb + j*240 + 8);
        lg[t][0] = fmaf(hv, w0.x, lg[t][0]);
        lg[t][1] = fmaf(hv, w0.y, lg[t][1]);
        lg[t][2] = fmaf(hv, w0.z, lg[t][2]);
        lg[t][3] = fmaf(hv, w0.w, lg[t][3]);
        lg[t][4] = fmaf(hv, w1.x, lg[t][4]);
        lg[t][5] = fmaf(hv, w1.y, lg[t][5]);
        lg[t][6] = fmaf(hv, w1.z, lg[t][6]);
        lg[t][7] = fmaf(hv, w1.w, lg[t][7]);
        lg[t][8] = fmaf(hv, w2v.x, lg[t][8]);
        lg[t][9] = fmaf(hv, w2v.y, lg[t][9]);
      }
    }
  }
  #pragma unroll
  for (int t = 0; t < 5; t++) {
    int task = tid + t * 256;
    int tok = task / 20, cg = task % 20;
    float l[10];
    #pragma unroll
    for (int c = 0; c < 10; c++) l[c] = lg[t][c] + b2[cg*10 + c];
    float mx = l[0];
    #pragma unroll
    for (int c = 1; c < 10; c++) mx = fmaxf(mx, l[c]);
    float sum = 0.0f, num = 0.0f;
    #pragma unroll
    for (int c = 0; c < 10; c++) {
      float e = expf(l[c] - mx);
      sum += e;
      num += (float)c * e;
    }
    float dig = num / sum;
    s->sDig[tok*20 + cg] = dig;
    int gtok = tok0 + tok;
    if (cg < 10) out[OFF_A + (long long)gtok*10 + cg]      = dig;
    else         out[OFF_B + (long long)gtok*10 + (cg-10)] = dig;
  }
  __syncthreads();

  // ============= modular decode of the selected op, per (token, prime) ======
  const int op = g_op[batch];
  if (op >= 0) {
    for (int task = tid; task < 64*9; task += 256) {
      int tok = task / 9, pr = task % 9;
      const float* dg = &s->sDig[tok*20];
      float ua = 0.0f, ub = 0.0f;
      #pragma unroll
      for (int k = 0; k < 10; k++) {
        float pw = d_P10F[pr][k];
        ua = fmaf(dg[k],    pw, ua);
        ub = fmaf(dg[10+k], pw, ub);
      }
      long long p = d_P[pr];
      float pf = (float)p;
      long long r;
      if (op == 0) {                                    // add
        r = llrintf(fmodf(ua + ub, pf)) % p;
      } else if (op == 1) {                             // sub (signed wrap)
        long long t = llrintf(fmodf(ua - ub, pf)) % p;
        r = (t + p) % p;
      } else {
        long long ra = llrintf(fmodf(ua, pf)) % p;
        long long rb = llrintf(fmodf(ub, pf)) % p;
        if (op == 2)      r = ra * rb % p;              // mul
        else if (op == 3) r = modpow6(ra, rb, p);       // exp
        else {                                          // div (Fermat inverse)
          long long inv = modpow6(rb, p - 2, p);
          r = (rb == 0) ? 0 : (ra * inv % p);
        }
      }
      s->sRes[tok*9 + pr] = (int)r;
    }
  }
  __syncthreads();

  // ===================== CRT + digits + msb reorder, per token ==============
  if (tid < 64) {
    long long d[10];
    float sign = 0.0f;
    if (op >= 0) {
      long long n = 0;
      #pragma unroll
      for (int pr = 0; pr < 9; pr++)
        n += (long long)s->sRes[tid*9 + pr] * d_CRT[pr];
      n %= M_TOT;
      if (op == 1 && n > M_HALF) n -= M_TOT;   // crt_signed only for sub
      long long a = (n < 0) ? -n : n;
      if (op == 1) sign = (n < 0) ? 1.0f : 0.0f;
      long long t = a;
      #pragma unroll
      for (int k = 0; k < 10; k++) { d[k] = t % 10; t /= 10; }
    } else {
      #pragma unroll
      for (int k = 0; k < 10; k++) d[k] = 0;
    }
    int hi = -1;
    #pragma unroll
    for (int k = 0; k < 10; k++) if (d[k] != 0) hi = k;
    int ns = (hi >= 0) ? hi + 1 : 1;
    #pragma unroll
    for (int i = 0; i < 10; i++)
      s->sMsb[tid*12 + i] = (i < ns) ? (float)d[ns-1-i] : -1.0f;
    s->sMsb[tid*12 + 10] = sign;
  }
  __syncthreads();

  // ================= inject: out = h + gate*eq*(msb@Winj + binj) ============
  float gl = gatep[0];
  float gate = (1.0f / (1.0f + expf(-gl))) * g_eq[batch];
  for (int tok = 0; tok < TM; tok++) {
    const float* mb = &s->sMsb[tok*12];
    long long base = (long long)(tok0 + tok) * DD;
    for (int dd = tid; dd < DD; dd += 256) {
      float inj = binj[dd];
      #pragma unroll
      for (int k = 0; k < 11; k++)
        inj = fmaf(mb[k], Winj[k*DD + dd], inj);
      out[base + dd] = h[base + dd] + gate * inj;
    }
  }
}

// ---------------------------------------------------------------------------
extern "C" void kernel_launch(void* const* d_in, const int* in_sizes, int n_in,
                              void* d_out, int out_size) {
  (void)in_sizes; (void)n_in; (void)out_size;
  const float* h    = (const float*)d_in[0];
  const float* W1   = (const float*)d_in[1];
  const float* b1   = (const float*)d_in[2];
  const float* W2   = (const float*)d_in[3];
  const float* b2   = (const float*)d_in[4];
  const float* Winj = (const float*)d_in[5];
  const float* binj = (const float*)d_in[6];
  const float* gate = (const float*)d_in[7];
  const int*   ids  = (const int*)d_in[8];   // int64 in JAX, delivered as int32
  float* out = (float*)d_out;

  prep_kernel<<<1, 512>>>(ids);

  size_t smem = sizeof(SmemT);
  cudaFuncSetAttribute(main_kernel, cudaFuncAttributeMaxDynamicSharedMemorySize,
                       (int)smem);
  main_kernel<<<NTOK / TM, 256, smem>>>(h, W1, b1, W2, b2, Winj, binj, gate, out);
}

// round 5
// speedup vs baseline: 2.0411x; 2.0411x over previous
#include <cuda_runtime.h>
#include <math.h>
#include <stdint.h>

#define BB   16
#define SS   2048
#define DD   768
#define MHID 128
#define NCLS 200
#define NTOK (BB*SS)
#define TM   128
#define NTHR 256
#define OFF_A ((long long)NTOK*DD)
#define OFF_B (OFF_A + (long long)NTOK*10)

#define M_TOT  247357937827LL
#define M_HALF 123678968913LL

// ---- SMEM byte offsets (dynamic) ----
// GEMM1 phase: A bufs (128x36 f32) + B bufs (32x136 f32), double buffered.
#define SM_A0   0
#define SM_A1   18432
#define SM_B0   36864
#define SM_B1   54272          // ends 71680
// Later phases (after GEMM1): W2 resident at 0 (122880 B), then:
#define SM_W2   0
#define SM_HID  122880         // 128*132*4 = 67584
#define SM_DIG  190464         // 128*20*4  = 10240
#define SM_RES  200704         // 128*9*4   = 4608
#define SM_MSB  205312         // 128*12*4  = 6144
#define SM_TOTAL 211456

#define A_STR 36               // floats per A row (32 + 4 pad)
#define B_STR 136              // floats per B row (128 + 8 pad)

static __device__ int   g_op[BB];
static __device__ float g_eq[BB];

__device__ const int d_P[9] = {7,11,13,17,19,23,29,31,37};
__device__ const float d_P10F[9][10] = {
  {1,3,2,6,4,5,1,3,2,6},
  {1,10,1,10,1,10,1,10,1,10},
  {1,10,9,12,3,4,1,10,9,12},
  {1,10,15,14,4,6,9,5,16,7},
  {1,10,5,12,6,3,11,15,17,18},
  {1,10,8,11,18,19,6,14,2,20},
  {1,10,13,14,24,8,22,17,25,18},
  {1,10,7,8,18,25,2,20,14,16},
  {1,10,26,1,10,26,1,10,26,1}};
__device__ const long long d_CRT[9] = {
  35336848261LL, 224870852570LL, 114165202074LL, 218257003965LL,
  78113032998LL, 53773464745LL, 68236672504LL, 223420072876LL,
  220616539143LL};

__device__ __forceinline__ float tf32r(float x) {
  uint32_t u;
  asm("cvt.rna.tf32.f32 %0, %1;" : "=r"(u) : "f"(x));
  return __uint_as_float(u);
}

__device__ __forceinline__ void mma_tf32(float* c, const uint32_t* a,
                                         const uint32_t* b) {
  asm volatile(
    "mma.sync.aligned.m16n8k8.row.col.f32.tf32.tf32.f32 "
    "{%0,%1,%2,%3}, {%4,%5,%6,%7}, {%8,%9}, {%0,%1,%2,%3};"
    : "+f"(c[0]), "+f"(c[1]), "+f"(c[2]), "+f"(c[3])
    : "r"(a[0]), "r"(a[1]), "r"(a[2]), "r"(a[3]), "r"(b[0]), "r"(b[1]));
}

__device__ __forceinline__ long long modpow6(long long base, long long e, long long p) {
  long long res = 1, b = base % p;
  #pragma unroll
  for (int i = 0; i < 6; i++) {
    if (e & 1) res = res * b % p;
    b = b * b % p;
    e >>= 1;
  }
  return res;
}

// ---------------------------------------------------------------------------
__global__ void prep_kernel(const int* __restrict__ ids) {
  int w = threadIdx.x >> 5, lane = threadIdx.x & 31;
  if (w >= BB) return;
  const int* row = ids + w * SS;
  int minpos = SS, eq = 0;
  for (int i = lane; i < SS; i += 32) {
    int t = row[i];
    eq |= (t == 28);
    if (t >= 20 && t <= 24) minpos = min(minpos, i);
  }
  #pragma unroll
  for (int off = 16; off; off >>= 1) {
    minpos = min(minpos, __shfl_xor_sync(0xffffffffu, minpos, off));
    eq    |= __shfl_xor_sync(0xffffffffu, eq, off);
  }
  if (lane == 0) {
    int pos = (minpos < SS) ? minpos : 0;
    int t = row[pos];
    g_op[w] = (t >= 20 && t <= 24) ? (t - 20) : -1;
    g_eq[w] = eq ? 1.0f : 0.0f;
  }
}

// ---------------------------------------------------------------------------
__global__ void __launch_bounds__(NTHR, 1)
main_kernel(const float* __restrict__ h,  const float* __restrict__ W1,
            const float* __restrict__ b1, const float* __restrict__ W2,
            const float* __restrict__ b2, const float* __restrict__ Winj,
            const float* __restrict__ binj, const float* __restrict__ gatep,
            float* __restrict__ out) {
  extern __shared__ char sm[];
  const int tid  = threadIdx.x;
  const int wid  = tid >> 5;
  const int lane = tid & 31;
  const int tok0 = blockIdx.x * TM;
  const int batch = tok0 / SS;

  float* sHid = (float*)(sm + SM_HID);   // [128][132]
  float* sW2  = (float*)(sm + SM_W2);    // [128][240] regrouped
  float* sDig = (float*)(sm + SM_DIG);
  int*   sRes = (int*)(sm + SM_RES);
  float* sMsb = (float*)(sm + SM_MSB);

  float* Ab[2] = {(float*)(sm + SM_A0), (float*)(sm + SM_A1)};
  float* Bb[2] = {(float*)(sm + SM_B0), (float*)(sm + SM_B1)};

  // ============ GEMM1 (tf32 mma.sync): hid = relu(h @ W1 + b1) =============
  const int g = lane >> 2, t = lane & 3;
  const int wm = wid & 3;            // warp row group: 32 tokens
  const int wn = wid >> 2;           // warp col group: 64 cols
  const int warp_row = wm * 32;
  const int warp_col = wn * 64;

  float acc[2][8][4];
  #pragma unroll
  for (int mt = 0; mt < 2; mt++)
    #pragma unroll
    for (int nt = 0; nt < 8; nt++)
      #pragma unroll
      for (int i = 0; i < 4; i++) acc[mt][nt][i] = 0.0f;

  // prologue: chunk 0 -> buf 0
  #pragma unroll
  for (int r = 0; r < 4; r++) {
    int idx = tid + r * 256;
    int ar = idx >> 3, ac4 = idx & 7;
    float4 v = *(const float4*)(h + (long long)(tok0 + ar) * DD + ac4 * 4);
    v.x = tf32r(v.x); v.y = tf32r(v.y); v.z = tf32r(v.z); v.w = tf32r(v.w);
    *(float4*)(Ab[0] + ar * A_STR + ac4 * 4) = v;
    int br = idx >> 5, bc4 = idx & 31;
    float4 w = *(const float4*)(W1 + br * MHID + bc4 * 4);
    w.x = tf32r(w.x); w.y = tf32r(w.y); w.z = tf32r(w.z); w.w = tf32r(w.w);
    *(float4*)(Bb[0] + br * B_STR + bc4 * 4) = w;
  }
  __syncthreads();

  for (int c = 0; c < 24; c++) {
    int cur = c & 1;
    float4 pa[4], pb[4];
    if (c < 23) {
      int k0n = (c + 1) * 32;
      #pragma unroll
      for (int r = 0; r < 4; r++) {
        int idx = tid + r * 256;
        int ar = idx >> 3, ac4 = idx & 7;
        pa[r] = *(const float4*)(h + (long long)(tok0 + ar) * DD + k0n + ac4 * 4);
        int br = idx >> 5, bc4 = idx & 31;
        pb[r] = *(const float4*)(W1 + (k0n + br) * MHID + bc4 * 4);
      }
    }
    // compute chunk c
    const float* A = Ab[cur];
    const float* B = Bb[cur];
    #pragma unroll
    for (int ks = 0; ks < 4; ks++) {
      uint32_t af[2][4];
      #pragma unroll
      for (int mt = 0; mt < 2; mt++) {
        const float* ap = A + (warp_row + mt * 16 + g) * A_STR + ks * 8 + t;
        af[mt][0] = __float_as_uint(ap[0]);
        af[mt][1] = __float_as_uint(ap[8 * A_STR]);
        af[mt][2] = __float_as_uint(ap[4]);
        af[mt][3] = __float_as_uint(ap[8 * A_STR + 4]);
      }
      uint32_t bf[8][2];
      #pragma unroll
      for (int nt = 0; nt < 8; nt++) {
        const float* bp = B + (ks * 8 + t) * B_STR + warp_col + nt * 8 + g;
        bf[nt][0] = __float_as_uint(bp[0]);
        bf[nt][1] = __float_as_uint(bp[4 * B_STR]);
      }
      #pragma unroll
      for (int mt = 0; mt < 2; mt++)
        #pragma unroll
        for (int nt = 0; nt < 8; nt++)
          mma_tf32(acc[mt][nt], af[mt], bf[nt]);
    }
    __syncthreads();
    if (c < 23) {
      int nxt = (c + 1) & 1;
      #pragma unroll
      for (int r = 0; r < 4; r++) {
        int idx = tid + r * 256;
        int ar = idx >> 3, ac4 = idx & 7;
        float4 v = pa[r];
        v.x = tf32r(v.x); v.y = tf32r(v.y); v.z = tf32r(v.z); v.w = tf32r(v.w);
        *(float4*)(Ab[nxt] + ar * A_STR + ac4 * 4) = v;
        int br = idx >> 5, bc4 = idx & 31;
        float4 w = pb[r];
        w.x = tf32r(w.x); w.y = tf32r(w.y); w.z = tf32r(w.z); w.w = tf32r(w.w);
        *(float4*)(Bb[nxt] + br * B_STR + bc4 * 4) = w;
      }
      __syncthreads();
    }
  }

  // ---- GEMM1 epilogue: bias + relu + tf32 round -> sHid ----
  #pragma unroll
  for (int mt = 0; mt < 2; mt++) {
    int row0 = warp_row + mt * 16 + g;
    #pragma unroll
    for (int nt = 0; nt < 8; nt++) {
      int col = warp_col + nt * 8 + 2 * t;
      float bx = b1[col], by = b1[col + 1];
      sHid[row0 * 132 + col]       = tf32r(fmaxf(acc[mt][nt][0] + bx, 0.0f));
      sHid[row0 * 132 + col + 1]   = tf32r(fmaxf(acc[mt][nt][1] + by, 0.0f));
      sHid[(row0+8) * 132 + col]   = tf32r(fmaxf(acc[mt][nt][2] + bx, 0.0f));
      sHid[(row0+8) * 132 + col+1] = tf32r(fmaxf(acc[mt][nt][3] + by, 0.0f));
    }
  }
  __syncthreads();

  // ---- load all of W2 into SMEM (regrouped [j][cg*12+c], tf32-rounded) ----
  for (int i4 = tid; i4 < 6400; i4 += NTHR) {   // 128 rows * 50 float4
    int j = i4 / 50, c4 = i4 % 50;
    float4 v = *(const float4*)(W2 + j * NCLS + c4 * 4);
    float vv[4] = {tf32r(v.x), tf32r(v.y), tf32r(v.z), tf32r(v.w)};
    #pragma unroll
    for (int u = 0; u < 4; u++) {
      int cc = c4 * 4 + u;
      sW2[j * 240 + (cc / 10) * 12 + (cc % 10)] = vv[u];
    }
  }
  __syncthreads();

  // ============== GEMM2 (SIMT) + softmax: 640 bundles of (cg, 4 toks) ======
  for (int bi = tid; bi < 640; bi += NTHR) {
    int cg = bi % 20, tg = bi / 20;
    float acc2[4][10];
    #pragma unroll
    for (int tt = 0; tt < 4; tt++)
      #pragma unroll
      for (int cc = 0; cc < 10; cc++) acc2[tt][cc] = 0.0f;

    const float* h0 = &sHid[(tg*4 + 0) * 132];
    const float* h1 = &sHid[(tg*4 + 1) * 132];
    const float* h2 = &sHid[(tg*4 + 2) * 132];
    const float* h3 = &sHid[(tg*4 + 3) * 132];
    const float* wbase = &sW2[cg * 12];

    for (int j4 = 0; j4 < 32; j4++) {
      float4 a0 = *(const float4*)(h0 + j4*4);
      float4 a1 = *(const float4*)(h1 + j4*4);
      float4 a2 = *(const float4*)(h2 + j4*4);
      float4 a3 = *(const float4*)(h3 + j4*4);
      const float* wr = wbase + (j4*4) * 240;
      #pragma unroll
      for (int jj = 0; jj < 4; jj++) {
        float4 wA = *(const float4*)(wr + jj*240);
        float4 wB = *(const float4*)(wr + jj*240 + 4);
        float2 wC = *(const float2*)(wr + jj*240 + 8);
        float w[10] = {wA.x,wA.y,wA.z,wA.w,wB.x,wB.y,wB.z,wB.w,wC.x,wC.y};
        float hv[4];
        hv[0] = (jj==0)?a0.x:(jj==1)?a0.y:(jj==2)?a0.z:a0.w;
        hv[1] = (jj==0)?a1.x:(jj==1)?a1.y:(jj==2)?a1.z:a1.w;
        hv[2] = (jj==0)?a2.x:(jj==1)?a2.y:(jj==2)?a2.z:a2.w;
        hv[3] = (jj==0)?a3.x:(jj==1)?a3.y:(jj==2)?a3.z:a3.w;
        #pragma unroll
        for (int tt = 0; tt < 4; tt++)
          #pragma unroll
          for (int cc = 0; cc < 10; cc++)
            acc2[tt][cc] = fmaf(hv[tt], w[cc], acc2[tt][cc]);
      }
    }
    #pragma unroll
    for (int tt = 0; tt < 4; tt++) {
      int tok = tg*4 + tt;
      float l[10];
      #pragma unroll
      for (int cc = 0; cc < 10; cc++) l[cc] = acc2[tt][cc] + b2[cg*10 + cc];
      float mx = l[0];
      #pragma unroll
      for (int cc = 1; cc < 10; cc++) mx = fmaxf(mx, l[cc]);
      float sum = 0.0f, num = 0.0f;
      #pragma unroll
      for (int cc = 0; cc < 10; cc++) {
        float e = expf(l[cc] - mx);
        sum += e; num += (float)cc * e;
      }
      float dig = num / sum;
      sDig[tok*20 + cg] = dig;
      long long gtok = tok0 + tok;
      if (cg < 10) out[OFF_A + gtok*10 + cg]      = dig;
      else         out[OFF_B + gtok*10 + (cg-10)] = dig;
    }
  }
  __syncthreads();

  // ============= modular decode of selected op, per (token, prime) =========
  const int op = g_op[batch];
  if (op >= 0) {
    for (int task = tid; task < TM*9; task += NTHR) {
      int tok = task / 9, pr = task % 9;
      const float* dg = &sDig[tok*20];
      float ua = 0.0f, ub = 0.0f;
      #pragma unroll
      for (int k = 0; k < 10; k++) {
        float pw = d_P10F[pr][k];
        ua = fmaf(dg[k],    pw, ua);
        ub = fmaf(dg[10+k], pw, ub);
      }
      long long p = d_P[pr];
      float pf = (float)p;
      long long r;
      if (op == 0) {
        r = llrintf(fmodf(ua + ub, pf)) % p;
      } else if (op == 1) {
        long long tt = llrintf(fmodf(ua - ub, pf)) % p;
        r = (tt + p) % p;
      } else {
        long long ra = llrintf(fmodf(ua, pf)) % p;
        long long rb = llrintf(fmodf(ub, pf)) % p;
        if (op == 2)      r = ra * rb % p;
        else if (op == 3) r = modpow6(ra, rb, p);
        else {
          long long inv = modpow6(rb, p - 2, p);
          r = (rb == 0) ? 0 : (ra * inv % p);
        }
      }
      sRes[tok*9 + pr] = (int)r;
    }
  }
  __syncthreads();

  // ===================== CRT + digits + msb reorder ========================
  if (tid < TM) {
    long long d[10];
    float sign = 0.0f;
    if (op >= 0) {
      long long n = 0;
      #pragma unroll
      for (int pr = 0; pr < 9; pr++)
        n += (long long)sRes[tid*9 + pr] * d_CRT[pr];
      n %= M_TOT;
      if (op == 1 && n > M_HALF) n -= M_TOT;
      long long a = (n < 0) ? -n : n;
      if (op == 1) sign = (n < 0) ? 1.0f : 0.0f;
      long long tt = a;
      #pragma unroll
      for (int k = 0; k < 10; k++) { d[k] = tt % 10; tt /= 10; }
    } else {
      #pragma unroll
      for (int k = 0; k < 10; k++) d[k] = 0;
    }
    int hi = -1;
    #pragma unroll
    for (int k = 0; k < 10; k++) if (d[k] != 0) hi = k;
    int ns = (hi >= 0) ? hi + 1 : 1;
    #pragma unroll
    for (int i = 0; i < 10; i++)
      sMsb[tid*12 + i] = (i < ns) ? (float)d[ns-1-i] : -1.0f;
    sMsb[tid*12 + 10] = sign;
  }
  __syncthreads();

  // ================= inject: out = h + gate*eq*(msb@Winj + binj) ===========
  {
    float gl = gatep[0];
    float gate = (1.0f / (1.0f + expf(-gl))) * g_eq[batch];
    float wreg[3][11], breg[3];
    #pragma unroll
    for (int r = 0; r < 3; r++) {
      int dd = tid + 256 * r;
      breg[r] = binj[dd];
      #pragma unroll
      for (int k = 0; k < 11; k++) wreg[r][k] = Winj[k * DD + dd];
    }
    for (int tok = 0; tok < TM; tok++) {
      float mb[11];
      #pragma unroll
      for (int k = 0; k < 11; k++) mb[k] = sMsb[tok*12 + k];
      long long base = (long long)(tok0 + tok) * DD;
      #pragma unroll
      for (int r = 0; r < 3; r++) {
        int dd = tid + 256 * r;
        float inj = breg[r];
        #pragma unroll
        for (int k = 0; k < 11; k++) inj = fmaf(mb[k], wreg[r][k], inj);
        out[base + dd] = h[base + dd] + gate * inj;
      }
    }
  }
}

// ---------------------------------------------------------------------------
extern "C" void kernel_launch(void* const* d_in, const int* in_sizes, int n_in,
                              void* d_out, int out_size) {
  (void)in_sizes; (void)n_in; (void)out_size;
  const float* h    = (const float*)d_in[0];
  const float* W1   = (const float*)d_in[1];
  const float* b1   = (const float*)d_in[2];
  const float* W2   = (const float*)d_in[3];
  const float* b2   = (const float*)d_in[4];
  const float* Winj = (const float*)d_in[5];
  const float* binj = (const float*)d_in[6];
  const float* gate = (const float*)d_in[7];
  const int*   ids  = (const int*)d_in[8];
  float* out = (float*)d_out;

  prep_kernel<<<1, 512>>>(ids);

  cudaFuncSetAttribute(main_kernel, cudaFuncAttributeMaxDynamicSharedMemorySize,
                       SM_TOTAL);
  main_kernel<<<NTOK / TM, NTHR, SM_TOTAL>>>(h, W1, b1, W2, b2, Winj, binj,
                                             gate, out);
}

// round 7
// speedup vs baseline: 2.2189x; 1.0871x over previous
#include <cuda_runtime.h>
#include <math.h>
#include <stdint.h>

#define BB   16
#define SS   2048
#define DD   768
#define MHID 128
#define NCLS 200
#define NTOK (BB*SS)
#define TM   128
#define NTHR 512
#define OFF_A ((long long)NTOK*DD)
#define OFF_B (OFF_A + (long long)NTOK*10)

#define M_TOT  247357937827LL
#define M_HALF 123678968913LL

// ---- SMEM byte offsets ----
#define SM_A0   0              // 128*36*4 = 18432
#define SM_A1   18432
#define SM_B0   36864          // 32*136*4 = 17408
#define SM_B1   54272          // ends 71680
#define SM_B2   0              // GEMM2 B pass buf: 128*136*4 = 69632 (reuses bufs)
#define SM_HID  71680          // 128*132*4 = 67584
#define SM_LOG  139264         // 128*104*4 = 53248
#define SM_DIG  192512         // 128*20*4  = 10240
#define SM_RES  202752         // 128*9*4   = 4608
#define SM_MSB  207360         // 128*12*4  = 6144
#define SM_TOTAL 213504

#define A_STR 36
#define B_STR 136
#define H_STR 132
#define L_STR 104

static __device__ int   g_op[BB];
static __device__ float g_eq[BB];

__device__ const int d_P[9] = {7,11,13,17,19,23,29,31,37};
__device__ const float d_P10F[9][10] = {
  {1,3,2,6,4,5,1,3,2,6},
  {1,10,1,10,1,10,1,10,1,10},
  {1,10,9,12,3,4,1,10,9,12},
  {1,10,15,14,4,6,9,5,16,7},
  {1,10,5,12,6,3,11,15,17,18},
  {1,10,8,11,18,19,6,14,2,20},
  {1,10,13,14,24,8,22,17,25,18},
  {1,10,7,8,18,25,2,20,14,16},
  {1,10,26,1,10,26,1,10,26,1}};
__device__ const long long d_CRT[9] = {
  35336848261LL, 224870852570LL, 114165202074LL, 218257003965LL,
  78113032998LL, 53773464745LL, 68236672504LL, 223420072876LL,
  220616539143LL};

__device__ __forceinline__ float tf32r(float x) {
  uint32_t u;
  asm("cvt.rna.tf32.f32 %0, %1;" : "=r"(u) : "f"(x));
  return __uint_as_float(u);
}

__device__ __forceinline__ void mma_tf32(float* c, const uint32_t* a,
                                         const uint32_t* b) {
  asm volatile(
    "mma.sync.aligned.m16n8k8.row.col.f32.tf32.tf32.f32 "
    "{%0,%1,%2,%3}, {%4,%5,%6,%7}, {%8,%9}, {%0,%1,%2,%3};"
    : "+f"(c[0]), "+f"(c[1]), "+f"(c[2]), "+f"(c[3])
    : "r"(a[0]), "r"(a[1]), "r"(a[2]), "r"(a[3]), "r"(b[0]), "r"(b[1]));
}

__device__ __forceinline__ long long modpow6(long long base, long long e, long long p) {
  long long res = 1, b = base % p;
  #pragma unroll
  for (int i = 0; i < 6; i++) {
    if (e & 1) res = res * b % p;
    b = b * b % p;
    e >>= 1;
  }
  return res;
}

// ---------------------------------------------------------------------------
__global__ void prep_kernel(const int* __restrict__ ids) {
  int w = threadIdx.x >> 5, lane = threadIdx.x & 31;
  if (w >= BB) return;
  const int* row = ids + w * SS;
  int minpos = SS, eq = 0;
  for (int i = lane; i < SS; i += 32) {
    int t = row[i];
    eq |= (t == 28);
    if (t >= 20 && t <= 24) minpos = min(minpos, i);
  }
  #pragma unroll
  for (int off = 16; off; off >>= 1) {
    minpos = min(minpos, __shfl_xor_sync(0xffffffffu, minpos, off));
    eq    |= __shfl_xor_sync(0xffffffffu, eq, off);
  }
  if (lane == 0) {
    int pos = (minpos < SS) ? minpos : 0;
    int t = row[pos];
    g_op[w] = (t >= 20 && t <= 24) ? (t - 20) : -1;
    g_eq[w] = eq ? 1.0f : 0.0f;
  }
}

// ---------------------------------------------------------------------------
__global__ void __launch_bounds__(NTHR, 1)
main_kernel(const float* __restrict__ h,  const float* __restrict__ W1,
            const float* __restrict__ b1, const float* __restrict__ W2,
            const float* __restrict__ b2, const float* __restrict__ Winj,
            const float* __restrict__ binj, const float* __restrict__ gatep,
            float* __restrict__ out) {
  extern __shared__ char sm[];
  const int tid  = threadIdx.x;
  const int wid  = tid >> 5;
  const int lane = tid & 31;
  const int tok0 = blockIdx.x * TM;
  const int batch = tok0 / SS;

  float* sHid = (float*)(sm + SM_HID);
  float* sLog = (float*)(sm + SM_LOG);
  float* sDig = (float*)(sm + SM_DIG);
  int*   sRes = (int*)(sm + SM_RES);
  float* sMsb = (float*)(sm + SM_MSB);
  float* Ab[2] = {(float*)(sm + SM_A0), (float*)(sm + SM_A1)};
  float* Bb[2] = {(float*)(sm + SM_B0), (float*)(sm + SM_B1)};
  float* B2 = (float*)(sm + SM_B2);

  // warp tiling: 4x4 warps, each 32 rows x 32 cols
  const int g = lane >> 2, t = lane & 3;
  const int warp_row = (wid & 3) * 32;
  const int warp_col = (wid >> 2) * 32;

  // ============ GEMM1 (tf32 mma.sync): hid = relu(h @ W1 + b1) =============
  float acc[2][4][4];
  #pragma unroll
  for (int mt = 0; mt < 2; mt++)
    #pragma unroll
    for (int nt = 0; nt < 4; nt++)
      #pragma unroll
      for (int i = 0; i < 4; i++) acc[mt][nt][i] = 0.0f;

  // prologue: chunk 0 -> buf 0   (A: 1024 f4, B: 1024 f4; 2 rounds @512thr)
  #pragma unroll
  for (int r = 0; r < 2; r++) {
    int idx = tid + r * 512;
    int ar = idx >> 3, ac4 = idx & 7;
    float4 v = *(const float4*)(h + (long long)(tok0 + ar) * DD + ac4 * 4);
    v.x = tf32r(v.x); v.y = tf32r(v.y); v.z = tf32r(v.z); v.w = tf32r(v.w);
    *(float4*)(Ab[0] + ar * A_STR + ac4 * 4) = v;
    int br = idx >> 5, bc4 = idx & 31;
    float4 w = *(const float4*)(W1 + br * MHID + bc4 * 4);
    w.x = tf32r(w.x); w.y = tf32r(w.y); w.z = tf32r(w.z); w.w = tf32r(w.w);
    *(float4*)(Bb[0] + br * B_STR + bc4 * 4) = w;
  }
  __syncthreads();

  for (int c = 0; c < 24; c++) {
    int cur = c & 1;
    float4 pa[2], pb[2];
    if (c < 23) {
      int k0n = (c + 1) * 32;
      #pragma unroll
      for (int r = 0; r < 2; r++) {
        int idx = tid + r * 512;
        int ar = idx >> 3, ac4 = idx & 7;
        pa[r] = *(const float4*)(h + (long long)(tok0 + ar) * DD + k0n + ac4 * 4);
        int br = idx >> 5, bc4 = idx & 31;
        pb[r] = *(const float4*)(W1 + (k0n + br) * MHID + bc4 * 4);
      }
    }
    const float* A = Ab[cur];
    const float* B = Bb[cur];
    #pragma unroll
    for (int ks = 0; ks < 4; ks++) {
      uint32_t af[2][4];
      #pragma unroll
      for (int mt = 0; mt < 2; mt++) {
        const float* ap = A + (warp_row + mt * 16 + g) * A_STR + ks * 8 + t;
        af[mt][0] = __float_as_uint(ap[0]);
        af[mt][1] = __float_as_uint(ap[8 * A_STR]);
        af[mt][2] = __float_as_uint(ap[4]);
        af[mt][3] = __float_as_uint(ap[8 * A_STR + 4]);
      }
      uint32_t bf[4][2];
      #pragma unroll
      for (int nt = 0; nt < 4; nt++) {
        const float* bp = B + (ks * 8 + t) * B_STR + warp_col + nt * 8 + g;
        bf[nt][0] = __float_as_uint(bp[0]);
        bf[nt][1] = __float_as_uint(bp[4 * B_STR]);
      }
      #pragma unroll
      for (int mt = 0; mt < 2; mt++)
        #pragma unroll
        for (int nt = 0; nt < 4; nt++)
          mma_tf32(acc[mt][nt], af[mt], bf[nt]);
    }
    __syncthreads();
    if (c < 23) {
      int nxt = (c + 1) & 1;
      #pragma unroll
      for (int r = 0; r < 2; r++) {
        int idx = tid + r * 512;
        int ar = idx >> 3, ac4 = idx & 7;
        float4 v = pa[r];
        v.x = tf32r(v.x); v.y = tf32r(v.y); v.z = tf32r(v.z); v.w = tf32r(v.w);
        *(float4*)(Ab[nxt] + ar * A_STR + ac4 * 4) = v;
        int br = idx >> 5, bc4 = idx & 31;
        float4 w = pb[r];
        w.x = tf32r(w.x); w.y = tf32r(w.y); w.z = tf32r(w.z); w.w = tf32r(w.w);
        *(float4*)(Bb[nxt] + br * B_STR + bc4 * 4) = w;
      }
      __syncthreads();
    }
  }
  __syncthreads();

  // ---- GEMM1 epilogue: bias + relu + tf32 -> sHid (A operand of GEMM2) ----
  #pragma unroll
  for (int mt = 0; mt < 2; mt++) {
    int row0 = warp_row + mt * 16 + g;
    #pragma unroll
    for (int nt = 0; nt < 4; nt++) {
      int col = warp_col + nt * 8 + 2 * t;
      float bx = b1[col], by = b1[col + 1];
      sHid[row0 * H_STR + col]       = tf32r(fmaxf(acc[mt][nt][0] + bx, 0.0f));
      sHid[row0 * H_STR + col + 1]   = tf32r(fmaxf(acc[mt][nt][1] + by, 0.0f));
      sHid[(row0+8) * H_STR + col]   = tf32r(fmaxf(acc[mt][nt][2] + bx, 0.0f));
      sHid[(row0+8) * H_STR + col+1] = tf32r(fmaxf(acc[mt][nt][3] + by, 0.0f));
    }
  }
  __syncthreads();

  // ============ GEMM2 (tf32 mma.sync) in 2 passes of 100 cols ==============
  for (int p = 0; p < 2; p++) {
    // load W2^T pass slice into B2: [k=128][B_STR], cols 0..99 real, 100..127 zero
    #pragma unroll
    for (int r = 0; r < 8; r++) {
      int idx = tid + r * 512;            // 4096 float4
      int br = idx >> 5, bc4 = idx & 31;
      float4 w;
      if (bc4 < 25) {
        w = *(const float4*)(W2 + br * NCLS + p * 100 + bc4 * 4);
        w.x = tf32r(w.x); w.y = tf32r(w.y); w.z = tf32r(w.z); w.w = tf32r(w.w);
      } else {
        w.x = w.y = w.z = w.w = 0.0f;
      }
      *(float4*)(B2 + br * B_STR + bc4 * 4) = w;
    }
    __syncthreads();

    #pragma unroll
    for (int mt = 0; mt < 2; mt++)
      #pragma unroll
      for (int nt = 0; nt < 4; nt++)
        #pragma unroll
        for (int i = 0; i < 4; i++) acc[mt][nt][i] = 0.0f;

    #pragma unroll 4
    for (int ks = 0; ks < 16; ks++) {
      uint32_t af[2][4];
      #pragma unroll
      for (int mt = 0; mt < 2; mt++) {
        const float* ap = sHid + (warp_row + mt * 16 + g) * H_STR + ks * 8 + t;
        af[mt][0] = __float_as_uint(ap[0]);
        af[mt][1] = __float_as_uint(ap[8 * H_STR]);
        af[mt][2] = __float_as_uint(ap[4]);
        af[mt][3] = __float_as_uint(ap[8 * H_STR + 4]);
      }
      uint32_t bf[4][2];
      #pragma unroll
      for (int nt = 0; nt < 4; nt++) {
        const float* bp = B2 + (ks * 8 + t) * B_STR + warp_col + nt * 8 + g;
        bf[nt][0] = __float_as_uint(bp[0]);
        bf[nt][1] = __float_as_uint(bp[4 * B_STR]);
      }
      #pragma unroll
      for (int mt = 0; mt < 2; mt++)
        #pragma unroll
        for (int nt = 0; nt < 4; nt++)
          mma_tf32(acc[mt][nt], af[mt], bf[nt]);
    }

    // epilogue: logits -> sLog (cols < 100)
    #pragma unroll
    for (int mt = 0; mt < 2; mt++) {
      int row0 = warp_row + mt * 16 + g;
      #pragma unroll
      for (int nt = 0; nt < 4; nt++) {
        int col = warp_col + nt * 8 + 2 * t;
        if (col < 100) {
          sLog[row0 * L_STR + col]       = acc[mt][nt][0];
          sLog[row0 * L_STR + col + 1]   = acc[mt][nt][1];
          sLog[(row0+8) * L_STR + col]   = acc[mt][nt][2];
          sLog[(row0+8) * L_STR + col+1] = acc[mt][nt][3];
        }
      }
    }
    __syncthreads();

    // softmax: 1280 tasks (tok, local col-group)
    for (int ti = tid; ti < 1280; ti += NTHR) {
      int tok = ti / 10, cgl = ti % 10;
      int cg = p * 10 + cgl;
      float l[10];
      #pragma unroll
      for (int cc = 0; cc < 10; cc++)
        l[cc] = sLog[tok * L_STR + cgl * 10 + cc] + b2[cg * 10 + cc];
      float mx = l[0];
      #pragma unroll
      for (int cc = 1; cc < 10; cc++) mx = fmaxf(mx, l[cc]);
      float sum = 0.0f, num = 0.0f;
      #pragma unroll
      for (int cc = 0; cc < 10; cc++) {
        float e = expf(l[cc] - mx);
        sum += e; num += (float)cc * e;
      }
      float dig = num / sum;
      sDig[tok * 20 + cg] = dig;
      long long gtok = tok0 + tok;
      if (cg < 10) out[OFF_A + gtok * 10 + cg]        = dig;
      else         out[OFF_B + gtok * 10 + (cg - 10)] = dig;
    }
    __syncthreads();
  }

  // ============= modular decode of selected op, per (token, prime) =========
  const int op = g_op[batch];
  if (op >= 0) {
    for (int task = tid; task < TM * 9; task += NTHR) {
      int tok = task / 9, pr = task % 9;
      const float* dg = &sDig[tok * 20];
      float ua = 0.0f, ub = 0.0f;
      #pragma unroll
      for (int k = 0; k < 10; k++) {
        float pw = d_P10F[pr][k];
        ua = fmaf(dg[k],      pw, ua);
        ub = fmaf(dg[10 + k], pw, ub);
      }
      long long pp = d_P[pr];
      float pf = (float)pp;
      long long r;
      if (op == 0) {
        r = llrintf(fmodf(ua + ub, pf)) % pp;
      } else if (op == 1) {
        long long tt = llrintf(fmodf(ua - ub, pf)) % pp;
        r = (tt + pp) % pp;
      } else {
        long long ra = llrintf(fmodf(ua, pf)) % pp;
        long long rb = llrintf(fmodf(ub, pf)) % pp;
        if (op == 2)      r = ra * rb % pp;
        else if (op == 3) r = modpow6(ra, rb, pp);
        else {
          long long inv = modpow6(rb, pp - 2, pp);
          r = (rb == 0) ? 0 : (ra * inv % pp);
        }
      }
      sRes[tok * 9 + pr] = (int)r;
    }
  }
  __syncthreads();

  // ===================== CRT + digits + msb reorder ========================
  if (tid < TM) {
    long long d[10];
    float sign = 0.0f;
    if (op >= 0) {
      long long n = 0;
      #pragma unroll
      for (int pr = 0; pr < 9; pr++)
        n += (long long)sRes[tid * 9 + pr] * d_CRT[pr];
      n %= M_TOT;
      if (op == 1 && n > M_HALF) n -= M_TOT;
      long long a = (n < 0) ? -n : n;
      if (op == 1) sign = (n < 0) ? 1.0f : 0.0f;
      long long tt = a;
      #pragma unroll
      for (int k = 0; k < 10; k++) { d[k] = tt % 10; tt /= 10; }
    } else {
      #pragma unroll
      for (int k = 0; k < 10; k++) d[k] = 0;
    }
    int hi = -1;
    #pragma unroll
    for (int k = 0; k < 10; k++) if (d[k] != 0) hi = k;
    int ns = (hi >= 0) ? hi + 1 : 1;
    #pragma unroll
    for (int i = 0; i < 10; i++)
      sMsb[tid * 12 + i] = (i < ns) ? (float)d[ns - 1 - i] : -1.0f;
    sMsb[tid * 12 + 10] = sign;
  }
  __syncthreads();

  // ================= inject: out = h + gate*eq*(msb@Winj + binj) ===========
  {
    float gl = gatep[0];
    float gate = (1.0f / (1.0f + expf(-gl))) * g_eq[batch];
    float wreg[2][11], breg[2];
    #pragma unroll
    for (int r = 0; r < 2; r++) {
      int dd = tid + NTHR * r;
      if (dd < DD) {
        breg[r] = binj[dd];
        #pragma unroll
        for (int k = 0; k < 11; k++) wreg[r][k] = Winj[k * DD + dd];
      }
    }
    for (int tok = 0; tok < TM; tok++) {
      float mb[11];
      #pragma unroll
      for (int k = 0; k < 11; k++) mb[k] = sMsb[tok * 12 + k];
      long long base = (long long)(tok0 + tok) * DD;
      #pragma unroll
      for (int r = 0; r < 2; r++) {
        int dd = tid + NTHR * r;
        if (dd < DD) {
          float inj = breg[r];
          #pragma unroll
          for (int k = 0; k < 11; k++) inj = fmaf(mb[k], wreg[r][k], inj);
          out[base + dd] = h[base + dd] + gate * inj;
        }
      }
    }
  }
}

// ---------------------------------------------------------------------------
extern "C" void kernel_launch(void* const* d_in, const int* in_sizes, int n_in,
                              void* d_out, int out_size) {
  (void)in_sizes; (void)n_in; (void)out_size;
  const float* h    = (const float*)d_in[0];
  const float* W1   = (const float*)d_in[1];
  const float* b1   = (const float*)d_in[2];
  const float* W2   = (const float*)d_in[3];
  const float* b2   = (const float*)d_in[4];
  const float* Winj = (const float*)d_in[5];
  const float* binj = (const float*)d_in[6];
  const float* gate = (const float*)d_in[7];
  const int*   ids  = (const int*)d_in[8];
  float* out = (float*)d_out;

  prep_kernel<<<1, 512>>>(ids);

  cudaFuncSetAttribute(main_kernel, cudaFuncAttributeMaxDynamicSharedMemorySize,
                       SM_TOTAL);
  main_kernel<<<NTOK / TM, NTHR, SM_TOTAL>>>(h, W1, b1, W2, b2, Winj, binj,
                                             gate, out);
}

// round 8
// speedup vs baseline: 2.5278x; 1.1392x over previous
#include <cuda_runtime.h>
#include <math.h>
#include <stdint.h>

#define BB   16
#define SS   2048
#define DD   768
#define MHID 128
#define NCLS 200
#define NTOK (BB*SS)
#define TM   64
#define NTHR 256
#define OFF_A ((long long)NTOK*DD)
#define OFF_B (OFF_A + (long long)NTOK*10)

#define M_TOT  247357937827LL
#define M_HALF 123678968913LL

// ---- SMEM layout ----
// transient union [0, 69632):
//   GEMM1: A0(9216) A1(9216) B0(17408) B1(17408) = 53248
//   GEMM2: B2 = 128*136*4 = 69632 ; then sLog = 64*104*4 = 26624 (aliases B2)
#define SM_A0   0
#define SM_A1   9216
#define SM_B0   18432
#define SM_B1   35840
#define SM_B2   0
#define SM_LOG  0
// persistent:
#define SM_HID  69632          // 64*132*4 = 33792
#define SM_DIG  103424         // 64*20*4  = 5120
#define SM_RES  108544         // 64*9*4   = 2304
#define SM_MSB  110848         // 64*12*4  = 3072
#define SM_TOTAL 113920

#define A_STR 36
#define B_STR 136
#define H_STR 132
#define L_STR 104

static __device__ int   g_op[BB];
static __device__ float g_eq[BB];

__device__ const int d_P[9] = {7,11,13,17,19,23,29,31,37};
__device__ const float d_P10F[9][10] = {
  {1,3,2,6,4,5,1,3,2,6},
  {1,10,1,10,1,10,1,10,1,10},
  {1,10,9,12,3,4,1,10,9,12},
  {1,10,15,14,4,6,9,5,16,7},
  {1,10,5,12,6,3,11,15,17,18},
  {1,10,8,11,18,19,6,14,2,20},
  {1,10,13,14,24,8,22,17,25,18},
  {1,10,7,8,18,25,2,20,14,16},
  {1,10,26,1,10,26,1,10,26,1}};
__device__ const long long d_CRT[9] = {
  35336848261LL, 224870852570LL, 114165202074LL, 218257003965LL,
  78113032998LL, 53773464745LL, 68236672504LL, 223420072876LL,
  220616539143LL};

__device__ __forceinline__ float tf32r(float x) {
  uint32_t u;
  asm("cvt.rna.tf32.f32 %0, %1;" : "=r"(u) : "f"(x));
  return __uint_as_float(u);
}

__device__ __forceinline__ void mma_tf32(float* c, const uint32_t* a,
                                         const uint32_t* b) {
  asm volatile(
    "mma.sync.aligned.m16n8k8.row.col.f32.tf32.tf32.f32 "
    "{%0,%1,%2,%3}, {%4,%5,%6,%7}, {%8,%9}, {%0,%1,%2,%3};"
    : "+f"(c[0]), "+f"(c[1]), "+f"(c[2]), "+f"(c[3])
    : "r"(a[0]), "r"(a[1]), "r"(a[2]), "r"(a[3]), "r"(b[0]), "r"(b[1]));
}

__device__ __forceinline__ long long modpow6(long long base, long long e, long long p) {
  long long res = 1, b = base % p;
  #pragma unroll
  for (int i = 0; i < 6; i++) {
    if (e & 1) res = res * b % p;
    b = b * b % p;
    e >>= 1;
  }
  return res;
}

// ---------------------------------------------------------------------------
__global__ void prep_kernel(const int* __restrict__ ids) {
  int w = threadIdx.x >> 5, lane = threadIdx.x & 31;
  if (w >= BB) return;
  const int* row = ids + w * SS;
  int minpos = SS, eq = 0;
  for (int i = lane; i < SS; i += 32) {
    int t = row[i];
    eq |= (t == 28);
    if (t >= 20 && t <= 24) minpos = min(minpos, i);
  }
  #pragma unroll
  for (int off = 16; off; off >>= 1) {
    minpos = min(minpos, __shfl_xor_sync(0xffffffffu, minpos, off));
    eq    |= __shfl_xor_sync(0xffffffffu, eq, off);
  }
  if (lane == 0) {
    int pos = (minpos < SS) ? minpos : 0;
    int t = row[pos];
    g_op[w] = (t >= 20 && t <= 24) ? (t - 20) : -1;
    g_eq[w] = eq ? 1.0f : 0.0f;
  }
}

// ---------------------------------------------------------------------------
__global__ void __launch_bounds__(NTHR, 2)
main_kernel(const float* __restrict__ h,  const float* __restrict__ W1,
            const float* __restrict__ b1, const float* __restrict__ W2,
            const float* __restrict__ b2, const float* __restrict__ Winj,
            const float* __restrict__ binj, const float* __restrict__ gatep,
            float* __restrict__ out) {
  extern __shared__ char sm[];
  const int tid  = threadIdx.x;
  const int wid  = tid >> 5;
  const int lane = tid & 31;
  const int tok0 = blockIdx.x * TM;
  const int batch = tok0 / SS;

  float* sHid = (float*)(sm + SM_HID);
  float* sLog = (float*)(sm + SM_LOG);
  float* sDig = (float*)(sm + SM_DIG);
  int*   sRes = (int*)(sm + SM_RES);
  float* sMsb = (float*)(sm + SM_MSB);
  float* Ab[2] = {(float*)(sm + SM_A0), (float*)(sm + SM_A1)};
  float* Bb[2] = {(float*)(sm + SM_B0), (float*)(sm + SM_B1)};
  float* B2 = (float*)(sm + SM_B2);

  // warp tiling: 2x4 warps, each 32 rows x 32 cols
  const int g = lane >> 2, t = lane & 3;
  const int warp_row = (wid & 1) * 32;
  const int warp_col = (wid >> 1) * 32;

  // ============ GEMM1 (tf32 mma.sync): hid = relu(h @ W1 + b1) =============
  float acc[2][4][4];
  #pragma unroll
  for (int mt = 0; mt < 2; mt++)
    #pragma unroll
    for (int nt = 0; nt < 4; nt++)
      #pragma unroll
      for (int i = 0; i < 4; i++) acc[mt][nt][i] = 0.0f;

  // prologue: chunk 0 -> buf 0  (A: 512 f4 -> 2 rounds; B: 1024 f4 -> 4 rounds)
  #pragma unroll
  for (int r = 0; r < 2; r++) {
    int idx = tid + r * 256;
    int ar = idx >> 3, ac4 = idx & 7;
    float4 v = *(const float4*)(h + (long long)(tok0 + ar) * DD + ac4 * 4);
    v.x = tf32r(v.x); v.y = tf32r(v.y); v.z = tf32r(v.z); v.w = tf32r(v.w);
    *(float4*)(Ab[0] + ar * A_STR + ac4 * 4) = v;
  }
  #pragma unroll
  for (int r = 0; r < 4; r++) {
    int idx = tid + r * 256;
    int br = idx >> 5, bc4 = idx & 31;
    float4 w = *(const float4*)(W1 + br * MHID + bc4 * 4);
    w.x = tf32r(w.x); w.y = tf32r(w.y); w.z = tf32r(w.z); w.w = tf32r(w.w);
    *(float4*)(Bb[0] + br * B_STR + bc4 * 4) = w;
  }
  __syncthreads();

  for (int c = 0; c < 24; c++) {
    int cur = c & 1;
    float4 pa[2], pb[4];
    if (c < 23) {
      int k0n = (c + 1) * 32;
      #pragma unroll
      for (int r = 0; r < 2; r++) {
        int idx = tid + r * 256;
        int ar = idx >> 3, ac4 = idx & 7;
        pa[r] = *(const float4*)(h + (long long)(tok0 + ar) * DD + k0n + ac4 * 4);
      }
      #pragma unroll
      for (int r = 0; r < 4; r++) {
        int idx = tid + r * 256;
        int br = idx >> 5, bc4 = idx & 31;
        pb[r] = *(const float4*)(W1 + (k0n + br) * MHID + bc4 * 4);
      }
    }
    const float* A = Ab[cur];
    const float* B = Bb[cur];
    #pragma unroll
    for (int ks = 0; ks < 4; ks++) {
      uint32_t af[2][4];
      #pragma unroll
      for (int mt = 0; mt < 2; mt++) {
        const float* ap = A + (warp_row + mt * 16 + g) * A_STR + ks * 8 + t;
        af[mt][0] = __float_as_uint(ap[0]);
        af[mt][1] = __float_as_uint(ap[8 * A_STR]);
        af[mt][2] = __float_as_uint(ap[4]);
        af[mt][3] = __float_as_uint(ap[8 * A_STR + 4]);
      }
      uint32_t bf[4][2];
      #pragma unroll
      for (int nt = 0; nt < 4; nt++) {
        const float* bp = B + (ks * 8 + t) * B_STR + warp_col + nt * 8 + g;
        bf[nt][0] = __float_as_uint(bp[0]);
        bf[nt][1] = __float_as_uint(bp[4 * B_STR]);
      }
      #pragma unroll
      for (int mt = 0; mt < 2; mt++)
        #pragma unroll
        for (int nt = 0; nt < 4; nt++)
          mma_tf32(acc[mt][nt], af[mt], bf[nt]);
    }
    __syncthreads();
    if (c < 23) {
      int nxt = (c + 1) & 1;
      #pragma unroll
      for (int r = 0; r < 2; r++) {
        int idx = tid + r * 256;
        int ar = idx >> 3, ac4 = idx & 7;
        float4 v = pa[r];
        v.x = tf32r(v.x); v.y = tf32r(v.y); v.z = tf32r(v.z); v.w = tf32r(v.w);
        *(float4*)(Ab[nxt] + ar * A_STR + ac4 * 4) = v;
      }
      #pragma unroll
      for (int r = 0; r < 4; r++) {
        int idx = tid + r * 256;
        int br = idx >> 5, bc4 = idx & 31;
        float4 w = pb[r];
        w.x = tf32r(w.x); w.y = tf32r(w.y); w.z = tf32r(w.z); w.w = tf32r(w.w);
        *(float4*)(Bb[nxt] + br * B_STR + bc4 * 4) = w;
      }
      __syncthreads();
    }
  }
  __syncthreads();

  // ---- GEMM1 epilogue: bias + relu + tf32 -> sHid (A operand of GEMM2) ----
  #pragma unroll
  for (int mt = 0; mt < 2; mt++) {
    int row0 = warp_row + mt * 16 + g;
    #pragma unroll
    for (int nt = 0; nt < 4; nt++) {
      int col = warp_col + nt * 8 + 2 * t;
      float bx = b1[col], by = b1[col + 1];
      sHid[row0 * H_STR + col]       = tf32r(fmaxf(acc[mt][nt][0] + bx, 0.0f));
      sHid[row0 * H_STR + col + 1]   = tf32r(fmaxf(acc[mt][nt][1] + by, 0.0f));
      sHid[(row0+8) * H_STR + col]   = tf32r(fmaxf(acc[mt][nt][2] + bx, 0.0f));
      sHid[(row0+8) * H_STR + col+1] = tf32r(fmaxf(acc[mt][nt][3] + by, 0.0f));
    }
  }
  __syncthreads();

  // ============ GEMM2 (tf32 mma.sync) in 2 passes of 100 cols ==============
  for (int p = 0; p < 2; p++) {
    // load W2^T pass slice into B2: [k=128][B_STR], cols 0..99 real, 100..127 zero
    #pragma unroll
    for (int r = 0; r < 16; r++) {
      int idx = tid + r * 256;            // 4096 float4
      int br = idx >> 5, bc4 = idx & 31;
      float4 w;
      if (bc4 < 25) {
        w = *(const float4*)(W2 + br * NCLS + p * 100 + bc4 * 4);
        w.x = tf32r(w.x); w.y = tf32r(w.y); w.z = tf32r(w.z); w.w = tf32r(w.w);
      } else {
        w.x = w.y = w.z = w.w = 0.0f;
      }
      *(float4*)(B2 + br * B_STR + bc4 * 4) = w;
    }
    __syncthreads();

    #pragma unroll
    for (int mt = 0; mt < 2; mt++)
      #pragma unroll
      for (int nt = 0; nt < 4; nt++)
        #pragma unroll
        for (int i = 0; i < 4; i++) acc[mt][nt][i] = 0.0f;

    #pragma unroll 4
    for (int ks = 0; ks < 16; ks++) {
      uint32_t af[2][4];
      #pragma unroll
      for (int mt = 0; mt < 2; mt++) {
        const float* ap = sHid + (warp_row + mt * 16 + g) * H_STR + ks * 8 + t;
        af[mt][0] = __float_as_uint(ap[0]);
        af[mt][1] = __float_as_uint(ap[8 * H_STR]);
        af[mt][2] = __float_as_uint(ap[4]);
        af[mt][3] = __float_as_uint(ap[8 * H_STR + 4]);
      }
      uint32_t bf[4][2];
      #pragma unroll
      for (int nt = 0; nt < 4; nt++) {
        const float* bp = B2 + (ks * 8 + t) * B_STR + warp_col + nt * 8 + g;
        bf[nt][0] = __float_as_uint(bp[0]);
        bf[nt][1] = __float_as_uint(bp[4 * B_STR]);
      }
      #pragma unroll
      for (int mt = 0; mt < 2; mt++)
        #pragma unroll
        for (int nt = 0; nt < 4; nt++)
          mma_tf32(acc[mt][nt], af[mt], bf[nt]);
    }
    __syncthreads();   // all warps done reading B2 before sLog overwrites it

    // epilogue: logits -> sLog (cols < 100; sLog aliases B2)
    #pragma unroll
    for (int mt = 0; mt < 2; mt++) {
      int row0 = warp_row + mt * 16 + g;
      #pragma unroll
      for (int nt = 0; nt < 4; nt++) {
        int col = warp_col + nt * 8 + 2 * t;
        if (col < 100) {
          sLog[row0 * L_STR + col]       = acc[mt][nt][0];
          sLog[row0 * L_STR + col + 1]   = acc[mt][nt][1];
          sLog[(row0+8) * L_STR + col]   = acc[mt][nt][2];
          sLog[(row0+8) * L_STR + col+1] = acc[mt][nt][3];
        }
      }
    }
    __syncthreads();

    // softmax: 640 tasks (tok, local col-group)
    for (int ti = tid; ti < TM * 10; ti += NTHR) {
      int tok = ti / 10, cgl = ti % 10;
      int cg = p * 10 + cgl;
      float l[10];
      #pragma unroll
      for (int cc = 0; cc < 10; cc++)
        l[cc] = sLog[tok * L_STR + cgl * 10 + cc] + b2[cg * 10 + cc];
      float mx = l[0];
      #pragma unroll
      for (int cc = 1; cc < 10; cc++) mx = fmaxf(mx, l[cc]);
      float sum = 0.0f, num = 0.0f;
      #pragma unroll
      for (int cc = 0; cc < 10; cc++) {
        float e = expf(l[cc] - mx);
        sum += e; num += (float)cc * e;
      }
      float dig = num / sum;
      sDig[tok * 20 + cg] = dig;
      long long gtok = tok0 + tok;
      if (cg < 10) out[OFF_A + gtok * 10 + cg]        = dig;
      else         out[OFF_B + gtok * 10 + (cg - 10)] = dig;
    }
    __syncthreads();
  }

  // ============= modular decode of selected op, per (token, prime) =========
  const int op = g_op[batch];
  if (op >= 0) {
    for (int task = tid; task < TM * 9; task += NTHR) {
      int tok = task / 9, pr = task % 9;
      const float* dg = &sDig[tok * 20];
      float ua = 0.0f, ub = 0.0f;
      #pragma unroll
      for (int k = 0; k < 10; k++) {
        float pw = d_P10F[pr][k];
        ua = fmaf(dg[k],      pw, ua);
        ub = fmaf(dg[10 + k], pw, ub);
      }
      long long pp = d_P[pr];
      float pf = (float)pp;
      long long r;
      if (op == 0) {
        r = llrintf(fmodf(ua + ub, pf)) % pp;
      } else if (op == 1) {
        long long tt = llrintf(fmodf(ua - ub, pf)) % pp;
        r = (tt + pp) % pp;
      } else {
        long long ra = llrintf(fmodf(ua, pf)) % pp;
        long long rb = llrintf(fmodf(ub, pf)) % pp;
        if (op == 2)      r = ra * rb % pp;
        else if (op == 3) r = modpow6(ra, rb, pp);
        else {
          long long inv = modpow6(rb, pp - 2, pp);
          r = (rb == 0) ? 0 : (ra * inv % pp);
        }
      }
      sRes[tok * 9 + pr] = (int)r;
    }
  }
  __syncthreads();

  // ===================== CRT + digits + msb reorder ========================
  if (tid < TM) {
    long long d[10];
    float sign = 0.0f;
    if (op >= 0) {
      long long n = 0;
      #pragma unroll
      for (int pr = 0; pr < 9; pr++)
        n += (long long)sRes[tid * 9 + pr] * d_CRT[pr];
      n %= M_TOT;
      if (op == 1 && n > M_HALF) n -= M_TOT;
      long long a = (n < 0) ? -n : n;
      if (op == 1) sign = (n < 0) ? 1.0f : 0.0f;
      long long tt = a;
      #pragma unroll
      for (int k = 0; k < 10; k++) { d[k] = tt % 10; tt /= 10; }
    } else {
      #pragma unroll
      for (int k = 0; k < 10; k++) d[k] = 0;
    }
    int hi = -1;
    #pragma unroll
    for (int k = 0; k < 10; k++) if (d[k] != 0) hi = k;
    int ns = (hi >= 0) ? hi + 1 : 1;
    #pragma unroll
    for (int i = 0; i < 10; i++)
      sMsb[tid * 12 + i] = (i < ns) ? (float)d[ns - 1 - i] : -1.0f;
    sMsb[tid * 12 + 10] = sign;
  }
  __syncthreads();

  // ================= inject: out = h + gate*eq*(msb@Winj + binj) ===========
  {
    float gl = gatep[0];
    float gate = (1.0f / (1.0f + expf(-gl))) * g_eq[batch];
    float wreg[3][11], breg[3];
    #pragma unroll
    for (int r = 0; r < 3; r++) {
      int dd = tid + NTHR * r;
      breg[r] = binj[dd];
      #pragma unroll
      for (int k = 0; k < 11; k++) wreg[r][k] = Winj[k * DD + dd];
    }
    for (int tok = 0; tok < TM; tok++) {
      float mb[11];
      #pragma unroll
      for (int k = 0; k < 11; k++) mb[k] = sMsb[tok * 12 + k];
      long long base = (long long)(tok0 + tok) * DD;
      #pragma unroll
      for (int r = 0; r < 3; r++) {
        int dd = tid + NTHR * r;
        float inj = breg[r];
        #pragma unroll
        for (int k = 0; k < 11; k++) inj = fmaf(mb[k], wreg[r][k], inj);
        out[base + dd] = h[base + dd] + gate * inj;
      }
    }
  }
}

// ---------------------------------------------------------------------------
extern "C" void kernel_launch(void* const* d_in, const int* in_sizes, int n_in,
                              void* d_out, int out_size) {
  (void)in_sizes; (void)n_in; (void)out_size;
  const float* h    = (const float*)d_in[0];
  const float* W1   = (const float*)d_in[1];
  const float* b1   = (const float*)d_in[2];
  const float* W2   = (const float*)d_in[3];
  const float* b2   = (const float*)d_in[4];
  const float* Winj = (const float*)d_in[5];
  const float* binj = (const float*)d_in[6];
  const float* gate = (const float*)d_in[7];
  const int*   ids  = (const int*)d_in[8];
  float* out = (float*)d_out;

  prep_kernel<<<1, 512>>>(ids);

  cudaFuncSetAttribute(main_kernel, cudaFuncAttributeMaxDynamicSharedMemorySize,
                       SM_TOTAL);
  main_kernel<<<NTOK / TM, NTHR, SM_TOTAL>>>(h, W1, b1, W2, b2, Winj, binj,
                                             gate, out);
}